// round 3
// baseline (speedup 1.0000x reference)
#include <cuda_runtime.h>
#include <math.h>

#define NN   10000
#define EE   160000
#define INC  512
#define OUTC 1024
#define ET   (EE + NN)

// ---------------- scratch (static device globals; no allocation) ----------------
__device__ float g_H1[NN * OUTC];     // x @ W1
__device__ float g_H2[NN * OUTC];     // x @ W2
__device__ float g_h1p[NN * OUTC];    // prelu(agg1 + b1)
__device__ float g_h2p[NN * OUTC];    // prelu(agg2 + b2)
__device__ float g_hs [NN * OUTC];    // h1p + h2p
__device__ float g_as1[NN];
__device__ float g_ad1[NN];
__device__ float g_as2[NN];
__device__ float g_ad2[NN];
__device__ int   g_deg[NN];
__device__ int   g_rowptr[NN + 1];
__device__ int   g_cursor[NN];
__device__ int   g_csrc[ET];
__device__ float g_csum[OUTC];
__device__ float g_att[OUTC];

// ---------------- init ----------------
__global__ void k_init() {
    int i = blockIdx.x * blockDim.x + threadIdx.x;
    if (i < NN) g_deg[i] = 0;
    if (i < OUTC) g_csum[i] = 0.0f;
}

// ---------------- CSR build ----------------
__global__ void k_count(const int* __restrict__ ei) {
    int i = blockIdx.x * blockDim.x + threadIdx.x;
    if (i >= ET) return;
    int d = (i < EE) ? ei[EE + i] : (i - EE);
    atomicAdd(&g_deg[d], 1);
}

__global__ void k_scan() {
    __shared__ int ssum[1024];
    int t = threadIdx.x;
    const int per = (NN + 1023) / 1024;  // 10
    int start = t * per;
    int local = 0;
    for (int i = 0; i < per; i++) {
        int idx = start + i;
        if (idx < NN) local += g_deg[idx];
    }
    ssum[t] = local;
    __syncthreads();
    for (int off = 1; off < 1024; off <<= 1) {
        int v = (t >= off) ? ssum[t - off] : 0;
        __syncthreads();
        ssum[t] += v;
        __syncthreads();
    }
    int run = (t == 0) ? 0 : ssum[t - 1];
    for (int i = 0; i < per; i++) {
        int idx = start + i;
        if (idx < NN) {
            g_rowptr[idx] = run;
            g_cursor[idx] = run;
            run += g_deg[idx];
        }
    }
    if (t == 1023) g_rowptr[NN] = run;
}

__global__ void k_scatter(const int* __restrict__ ei) {
    int i = blockIdx.x * blockDim.x + threadIdx.x;
    if (i >= ET) return;
    int s, d;
    if (i < EE) { s = ei[i]; d = ei[EE + i]; }
    else        { s = i - EE; d = s; }
    int pos = atomicAdd(&g_cursor[d], 1);
    g_csrc[pos] = s;
}

// ---------------- fp32 tiled GEMM: C[M,N] = A[M,K] @ B[K,N] ----------------
// BM=BN=128, BK=16, 256 threads, 8x8 per thread. N,K multiples of 16; M guarded.
__global__ __launch_bounds__(256)
void sgemm(const float* __restrict__ A, const float* __restrict__ B,
           float* __restrict__ C, int M, int N, int K) {
    __shared__ float As[16][128];
    __shared__ float Bs[16][128];
    int tid = threadIdx.x;
    int tx = tid & 15;
    int ty = tid >> 4;
    int bn = blockIdx.x * 128;
    int bm = blockIdx.y * 128;

    float acc[8][8];
#pragma unroll
    for (int i = 0; i < 8; i++)
#pragma unroll
        for (int j = 0; j < 8; j++) acc[i][j] = 0.0f;

    int arow = tid >> 2;          // 0..63
    int acol = (tid & 3) << 2;    // 0,4,8,12
    int brow = tid >> 5;          // 0..7
    int bcol = (tid & 31) << 2;   // 0..124

    for (int kt = 0; kt < K; kt += 16) {
#pragma unroll
        for (int r = 0; r < 128; r += 64) {
            int grow = bm + arow + r;
            float4 v = make_float4(0.f, 0.f, 0.f, 0.f);
            if (grow < M) v = *(const float4*)(A + (size_t)grow * K + kt + acol);
            As[acol + 0][arow + r] = v.x;
            As[acol + 1][arow + r] = v.y;
            As[acol + 2][arow + r] = v.z;
            As[acol + 3][arow + r] = v.w;
        }
#pragma unroll
        for (int r = 0; r < 16; r += 8) {
            float4 v = *(const float4*)(B + (size_t)(kt + brow + r) * N + bn + bcol);
            *(float4*)&Bs[brow + r][bcol] = v;
        }
        __syncthreads();
#pragma unroll
        for (int k = 0; k < 16; k++) {
            float rm[8], rn[8];
#pragma unroll
            for (int i = 0; i < 8; i++) rm[i] = As[k][ty * 8 + i];
#pragma unroll
            for (int j = 0; j < 8; j++) rn[j] = Bs[k][tx * 8 + j];
#pragma unroll
            for (int i = 0; i < 8; i++)
#pragma unroll
                for (int j = 0; j < 8; j++) acc[i][j] += rm[i] * rn[j];
        }
        __syncthreads();
    }
#pragma unroll
    for (int i = 0; i < 8; i++) {
        int grow = bm + ty * 8 + i;
        if (grow < M) {
#pragma unroll
            for (int j = 0; j < 8; j += 4) {
                float4 v = make_float4(acc[i][j], acc[i][j + 1], acc[i][j + 2], acc[i][j + 3]);
                *(float4*)(C + (size_t)grow * N + bn + tx * 8 + j) = v;
            }
        }
    }
}

// ---------------- GEMM variant: column-sum of tanh(A@B + bias), no C stored ----
__global__ __launch_bounds__(256)
void sgemm_tanh_colsum(const float* __restrict__ A, const float* __restrict__ B,
                       const float* __restrict__ bias, int M, int N, int K) {
    __shared__ float As[16][128];
    __shared__ float Bs[16][128];
    int tid = threadIdx.x;
    int tx = tid & 15;
    int ty = tid >> 4;
    int bn = blockIdx.x * 128;
    int bm = blockIdx.y * 128;

    float acc[8][8];
#pragma unroll
    for (int i = 0; i < 8; i++)
#pragma unroll
        for (int j = 0; j < 8; j++) acc[i][j] = 0.0f;

    int arow = tid >> 2;
    int acol = (tid & 3) << 2;
    int brow = tid >> 5;
    int bcol = (tid & 31) << 2;

    for (int kt = 0; kt < K; kt += 16) {
#pragma unroll
        for (int r = 0; r < 128; r += 64) {
            int grow = bm + arow + r;
            float4 v = make_float4(0.f, 0.f, 0.f, 0.f);
            if (grow < M) v = *(const float4*)(A + (size_t)grow * K + kt + acol);
            As[acol + 0][arow + r] = v.x;
            As[acol + 1][arow + r] = v.y;
            As[acol + 2][arow + r] = v.z;
            As[acol + 3][arow + r] = v.w;
        }
#pragma unroll
        for (int r = 0; r < 16; r += 8) {
            float4 v = *(const float4*)(B + (size_t)(kt + brow + r) * N + bn + bcol);
            *(float4*)&Bs[brow + r][bcol] = v;
        }
        __syncthreads();
#pragma unroll
        for (int k = 0; k < 16; k++) {
            float rm[8], rn[8];
#pragma unroll
            for (int i = 0; i < 8; i++) rm[i] = As[k][ty * 8 + i];
#pragma unroll
            for (int j = 0; j < 8; j++) rn[j] = Bs[k][tx * 8 + j];
#pragma unroll
            for (int i = 0; i < 8; i++)
#pragma unroll
                for (int j = 0; j < 8; j++) acc[i][j] += rm[i] * rn[j];
        }
        __syncthreads();
    }

    // epilogue: tanh(acc + bias[col]) summed over the (valid) rows of this tile
    float bj[8];
#pragma unroll
    for (int j = 0; j < 8; j++) bj[j] = bias[bn + tx * 8 + j];

    float cl[8];
#pragma unroll
    for (int j = 0; j < 8; j++) cl[j] = 0.0f;
#pragma unroll
    for (int i = 0; i < 8; i++) {
        int grow = bm + ty * 8 + i;
        if (grow < M) {
#pragma unroll
            for (int j = 0; j < 8; j++) cl[j] += tanhf(acc[i][j] + bj[j]);
        }
    }

    __shared__ float red[16][128];
#pragma unroll
    for (int j = 0; j < 8; j++) red[ty][tx * 8 + j] = cl[j];
    __syncthreads();
    if (ty == 0) {
#pragma unroll
        for (int j = 0; j < 8; j++) {
            int col = tx * 8 + j;
            float s = 0.0f;
#pragma unroll
            for (int t = 0; t < 16; t++) s += red[t][col];
            atomicAdd(&g_csum[bn + col], s);
        }
    }
}

// ---------------- per-node attention logit dots ----------------
__global__ __launch_bounds__(256)
void k_rowdots(const float* __restrict__ a_s1, const float* __restrict__ a_d1,
               const float* __restrict__ a_s2, const float* __restrict__ a_d2) {
    int n = blockIdx.x;
    int tid = threadIdx.x;
    const float* h1 = g_H1 + (size_t)n * OUTC;
    const float* h2 = g_H2 + (size_t)n * OUTC;
    float p1 = 0.f, p2 = 0.f, p3 = 0.f, p4 = 0.f;
    for (int c = tid; c < OUTC; c += 256) {
        float v1 = h1[c], v2 = h2[c];
        p1 += v1 * a_s1[c];
        p2 += v1 * a_d1[c];
        p3 += v2 * a_s2[c];
        p4 += v2 * a_d2[c];
    }
    __shared__ float sr[4][256];
    sr[0][tid] = p1; sr[1][tid] = p2; sr[2][tid] = p3; sr[3][tid] = p4;
    __syncthreads();
    for (int o = 128; o > 0; o >>= 1) {
        if (tid < o) {
#pragma unroll
            for (int q = 0; q < 4; q++) sr[q][tid] += sr[q][tid + o];
        }
        __syncthreads();
    }
    if (tid == 0) {
        g_as1[n] = sr[0][0];
        g_ad1[n] = sr[1][0];
        g_as2[n] = sr[2][0];
        g_ad2[n] = sr[3][0];
    }
}

// ---------------- per-dst-node segment softmax + weighted aggregation ----------
__global__ __launch_bounds__(256)
void k_agg(const float* __restrict__ b1, const float* __restrict__ b2,
           const float* __restrict__ prelu_a) {
    int d = blockIdx.x;
    int tid = threadIdx.x;
    int beg = g_rowptr[d];
    int deg = g_rowptr[d + 1] - beg;
    float ad1 = g_ad1[d];
    float ad2 = g_ad2[d];

    __shared__ float r1[256];
    __shared__ float r2[256];

    // phase A: segment max of leakyrelu(e)
    float m1 = -1e30f, m2 = -1e30f;
    for (int i = tid; i < deg; i += 256) {
        int s = g_csrc[beg + i];
        float e1 = g_as1[s] + ad1; e1 = (e1 >= 0.f) ? e1 : 0.2f * e1;
        float e2 = g_as2[s] + ad2; e2 = (e2 >= 0.f) ? e2 : 0.2f * e2;
        m1 = fmaxf(m1, e1);
        m2 = fmaxf(m2, e2);
    }
    r1[tid] = m1; r2[tid] = m2;
    __syncthreads();
    for (int o = 128; o > 0; o >>= 1) {
        if (tid < o) {
            r1[tid] = fmaxf(r1[tid], r1[tid + o]);
            r2[tid] = fmaxf(r2[tid], r2[tid + o]);
        }
        __syncthreads();
    }
    float M1 = r1[0], M2 = r2[0];
    __syncthreads();

    // phase B: segment sum of exp
    float s1 = 0.f, s2 = 0.f;
    for (int i = tid; i < deg; i += 256) {
        int s = g_csrc[beg + i];
        float e1 = g_as1[s] + ad1; e1 = (e1 >= 0.f) ? e1 : 0.2f * e1;
        float e2 = g_as2[s] + ad2; e2 = (e2 >= 0.f) ? e2 : 0.2f * e2;
        s1 += expf(e1 - M1);
        s2 += expf(e2 - M2);
    }
    r1[tid] = s1; r2[tid] = s2;
    __syncthreads();
    for (int o = 128; o > 0; o >>= 1) {
        if (tid < o) {
            r1[tid] += r1[tid + o];
            r2[tid] += r2[tid + o];
        }
        __syncthreads();
    }
    float inv1 = 1.f / r1[0];
    float inv2 = 1.f / r2[0];
    __syncthreads();

    // phase C: weighted gather-accumulate; thread owns 4 contiguous channels
    __shared__ int   sS[128];
    __shared__ float sA1[128];
    __shared__ float sA2[128];

    int c = tid * 4;
    float4 acc1 = make_float4(0.f, 0.f, 0.f, 0.f);
    float4 acc2 = make_float4(0.f, 0.f, 0.f, 0.f);

    for (int base = 0; base < deg; base += 128) {
        int cn = min(128, deg - base);
        if (tid < cn) {
            int s = g_csrc[beg + base + tid];
            float e1 = g_as1[s] + ad1; e1 = (e1 >= 0.f) ? e1 : 0.2f * e1;
            float e2 = g_as2[s] + ad2; e2 = (e2 >= 0.f) ? e2 : 0.2f * e2;
            sS[tid]  = s;
            sA1[tid] = expf(e1 - M1) * inv1;
            sA2[tid] = expf(e2 - M2) * inv2;
        }
        __syncthreads();
        for (int i = 0; i < cn; i++) {
            int s = sS[i];
            float a1 = sA1[i], a2 = sA2[i];
            float4 v1 = *(const float4*)(g_H1 + (size_t)s * OUTC + c);
            float4 v2 = *(const float4*)(g_H2 + (size_t)s * OUTC + c);
            acc1.x += a1 * v1.x; acc1.y += a1 * v1.y; acc1.z += a1 * v1.z; acc1.w += a1 * v1.w;
            acc2.x += a2 * v2.x; acc2.y += a2 * v2.y; acc2.z += a2 * v2.z; acc2.w += a2 * v2.w;
        }
        __syncthreads();
    }

    // epilogue: bias + PReLU, write h1p/h2p/hs
    float pa = *prelu_a;
    float4 bb1 = *(const float4*)(b1 + c);
    float4 bb2 = *(const float4*)(b2 + c);
    float4 h1, h2, hs;
    h1.x = acc1.x + bb1.x; h1.y = acc1.y + bb1.y; h1.z = acc1.z + bb1.z; h1.w = acc1.w + bb1.w;
    h2.x = acc2.x + bb2.x; h2.y = acc2.y + bb2.y; h2.z = acc2.z + bb2.z; h2.w = acc2.w + bb2.w;
    h1.x = (h1.x >= 0.f) ? h1.x : pa * h1.x;
    h1.y = (h1.y >= 0.f) ? h1.y : pa * h1.y;
    h1.z = (h1.z >= 0.f) ? h1.z : pa * h1.z;
    h1.w = (h1.w >= 0.f) ? h1.w : pa * h1.w;
    h2.x = (h2.x >= 0.f) ? h2.x : pa * h2.x;
    h2.y = (h2.y >= 0.f) ? h2.y : pa * h2.y;
    h2.z = (h2.z >= 0.f) ? h2.z : pa * h2.z;
    h2.w = (h2.w >= 0.f) ? h2.w : pa * h2.w;
    hs.x = h1.x + h2.x; hs.y = h1.y + h2.y; hs.z = h1.z + h2.z; hs.w = h1.w + h2.w;

    size_t off = (size_t)d * OUTC + c;
    *(float4*)(g_h1p + off) = h1;
    *(float4*)(g_h2p + off) = h2;
    *(float4*)(g_hs + off)  = hs;
}

// ---------------- semantic attention: w = (csum/N) @ Wp2, softmax ----------------
__global__ __launch_bounds__(256)
void k_att(const float* __restrict__ Wp2) {
    __shared__ float tb[OUTC];
    int tid = threadIdx.x;
    for (int i = tid; i < OUTC; i += 256) tb[i] = g_csum[i] * (1.0f / (float)NN);
    __syncthreads();
    int j0 = tid * 4;
    float4 w = make_float4(0.f, 0.f, 0.f, 0.f);
    for (int i = 0; i < OUTC; i++) {
        float t = tb[i];
        float4 v = *(const float4*)(Wp2 + (size_t)i * OUTC + j0);
        w.x += t * v.x; w.y += t * v.y; w.z += t * v.z; w.w += t * v.w;
    }
    __shared__ float rr[256];
    float lm = fmaxf(fmaxf(w.x, w.y), fmaxf(w.z, w.w));
    rr[tid] = lm;
    __syncthreads();
    for (int o = 128; o > 0; o >>= 1) {
        if (tid < o) rr[tid] = fmaxf(rr[tid], rr[tid + o]);
        __syncthreads();
    }
    float M = rr[0];
    __syncthreads();
    float ex = expf(w.x - M), ey = expf(w.y - M), ez = expf(w.z - M), ew = expf(w.w - M);
    rr[tid] = ex + ey + ez + ew;
    __syncthreads();
    for (int o = 128; o > 0; o >>= 1) {
        if (tid < o) rr[tid] += rr[tid + o];
        __syncthreads();
    }
    float inv = 1.f / rr[0];
    *(float4*)(g_att + j0) = make_float4(ex * inv, ey * inv, ez * inv, ew * inv);
}

// ---------------- final blend ----------------
__global__ void k_final(float* __restrict__ out) {
    int i = blockIdx.x * blockDim.x + threadIdx.x;  // float4 index
    if (i >= NN * OUTC / 4) return;
    int cg = i & (OUTC / 4 - 1);
    float4 a  = *(const float4*)(g_att + cg * 4);
    float4 h1 = ((const float4*)g_h1p)[i];
    float4 h2 = ((const float4*)g_h2p)[i];
    float4 o;
    o.x = a.x * h1.x + (1.f - a.x) * h2.x;
    o.y = a.y * h1.y + (1.f - a.y) * h2.y;
    o.z = a.z * h1.z + (1.f - a.z) * h2.z;
    o.w = a.w * h1.w + (1.f - a.w) * h2.w;
    ((float4*)out)[i] = o;
}

// ---------------- launch ----------------
extern "C" void kernel_launch(void* const* d_in, const int* in_sizes, int n_in,
                              void* d_out, int out_size) {
    const float* x      = (const float*)d_in[0];
    const int*   ei     = (const int*)d_in[1];
    const float* W1     = (const float*)d_in[2];
    const float* a_src1 = (const float*)d_in[3];
    const float* a_dst1 = (const float*)d_in[4];
    const float* b1     = (const float*)d_in[5];
    const float* W2     = (const float*)d_in[6];
    const float* a_src2 = (const float*)d_in[7];
    const float* a_dst2 = (const float*)d_in[8];
    const float* b2     = (const float*)d_in[9];
    const float* prelua = (const float*)d_in[10];
    const float* Wp1    = (const float*)d_in[11];
    const float* bp1    = (const float*)d_in[12];
    const float* Wp2    = (const float*)d_in[13];
    float* out = (float*)d_out;

    float *H1, *H2, *HS;
    cudaGetSymbolAddress((void**)&H1, g_H1);
    cudaGetSymbolAddress((void**)&H2, g_H2);
    cudaGetSymbolAddress((void**)&HS, g_hs);

    dim3 ggrid(OUTC / 128, (NN + 127) / 128);

    k_init<<<(NN + 255) / 256, 256>>>();
    sgemm<<<ggrid, 256>>>(x, W1, H1, NN, OUTC, INC);
    sgemm<<<ggrid, 256>>>(x, W2, H2, NN, OUTC, INC);
    k_rowdots<<<NN, 256>>>(a_src1, a_dst1, a_src2, a_dst2);
    k_count<<<(ET + 255) / 256, 256>>>(ei);
    k_scan<<<1, 1024>>>();
    k_scatter<<<(ET + 255) / 256, 256>>>(ei);
    k_agg<<<NN, 256>>>(b1, b2, prelua);
    sgemm_tanh_colsum<<<ggrid, 256>>>(HS, Wp1, bp1, NN, OUTC, OUTC);
    k_att<<<1, 256>>>(Wp2);
    k_final<<<(NN * OUTC / 4 + 255) / 256, 256>>>(out);
}

// round 5
// speedup vs baseline: 1.4775x; 1.4775x over previous
#include <cuda_runtime.h>
#include <cuda_bf16.h>
#include <math.h>

#define NN   10000
#define EE   160000
#define INC  512
#define OUTC 1024
#define ET   (EE + NN)

// ---------------- scratch (static device globals; no allocation) ----------------
__device__ float g_H1[NN * OUTC];     // x @ W1
__device__ float g_H2[NN * OUTC];     // x @ W2
__device__ float g_h1p[NN * OUTC];    // prelu(agg1 + b1)
__device__ float g_h2p[NN * OUTC];    // prelu(agg2 + b2)
__device__ float g_as1[NN];
__device__ float g_ad1[NN];
__device__ float g_as2[NN];
__device__ float g_ad2[NN];
__device__ float g_wa[4][INC];        // W1@a_src1, W1@a_dst1, W2@a_src2, W2@a_dst2
__device__ int   g_deg[NN];
__device__ int   g_rowptr[NN + 1];
__device__ int   g_cursor[NN];
__device__ int   g_csrc[ET];
__device__ float g_csum[OUTC];
__device__ float g_att[OUTC];

// ---------------- init ----------------
__global__ void k_init() {
    int i = blockIdx.x * blockDim.x + threadIdx.x;
    if (i < NN) g_deg[i] = 0;
    if (i < OUTC) g_csum[i] = 0.0f;
}

// ---------------- CSR build ----------------
__global__ void k_count(const int* __restrict__ ei) {
    int i = blockIdx.x * blockDim.x + threadIdx.x;
    if (i >= ET) return;
    int d = (i < EE) ? ei[EE + i] : (i - EE);
    atomicAdd(&g_deg[d], 1);
}

__global__ void k_scan() {
    __shared__ int ssum[1024];
    int t = threadIdx.x;
    const int per = (NN + 1023) / 1024;  // 10
    int start = t * per;
    int local = 0;
    for (int i = 0; i < per; i++) {
        int idx = start + i;
        if (idx < NN) local += g_deg[idx];
    }
    ssum[t] = local;
    __syncthreads();
    for (int off = 1; off < 1024; off <<= 1) {
        int v = (t >= off) ? ssum[t - off] : 0;
        __syncthreads();
        ssum[t] += v;
        __syncthreads();
    }
    int run = (t == 0) ? 0 : ssum[t - 1];
    for (int i = 0; i < per; i++) {
        int idx = start + i;
        if (idx < NN) {
            g_rowptr[idx] = run;
            g_cursor[idx] = run;
            run += g_deg[idx];
        }
    }
    if (t == 1023) g_rowptr[NN] = run;
}

__global__ void k_scatter(const int* __restrict__ ei) {
    int i = blockIdx.x * blockDim.x + threadIdx.x;
    if (i >= ET) return;
    int s, d;
    if (i < EE) { s = ei[i]; d = ei[EE + i]; }
    else        { s = i - EE; d = s; }
    int pos = atomicAdd(&g_cursor[d], 1);
    g_csrc[pos] = s;
}

// ---------------- W@a precompute: g_wa[p] = W_p @ a_p  (4 vectors of 512) ------
__global__ __launch_bounds__(256)
void k_wa(const float* __restrict__ W1, const float* __restrict__ as1,
          const float* __restrict__ ad1,
          const float* __restrict__ W2, const float* __restrict__ as2,
          const float* __restrict__ ad2) {
    int p   = blockIdx.x >> 2;   // 0..3
    int seg = blockIdx.x & 3;    // 128 rows per segment
    const float* W = (p < 2) ? W1 : W2;
    const float* a = (p == 0) ? as1 : (p == 1) ? ad1 : (p == 2) ? as2 : ad2;
    int t = threadIdx.x;
    int row = seg * 128 + (t >> 1);
    int half = t & 1;
    const float* wr = W + (size_t)row * OUTC + half * 512;
    const float* av = a + half * 512;
    float s = 0.f;
    for (int j = 0; j < 512; j += 4) {
        float4 w4 = *(const float4*)(wr + j);
        float4 a4 = *(const float4*)(av + j);
        s += w4.x * a4.x + w4.y * a4.y + w4.z * a4.z + w4.w * a4.w;
    }
    s += __shfl_xor_sync(0xffffffffu, s, 1);
    if (half == 0) g_wa[p][row] = s;
}

// ---------------- per-node attention logits: as/ad = x @ (W@a) ------------------
__global__ __launch_bounds__(256)
void k_xdots(const float* __restrict__ x) {
    int w = threadIdx.x >> 5;
    int lane = threadIdx.x & 31;
    int n = blockIdx.x * 8 + w;           // NN = 10000 = 1250*8
    const float4* xr = (const float4*)(x + (size_t)n * INC);
    float s0 = 0.f, s1 = 0.f, s2 = 0.f, s3 = 0.f;
#pragma unroll
    for (int i = lane; i < INC / 4; i += 32) {
        float4 xv = xr[i];
        float4 v0 = ((const float4*)g_wa[0])[i];
        float4 v1 = ((const float4*)g_wa[1])[i];
        float4 v2 = ((const float4*)g_wa[2])[i];
        float4 v3 = ((const float4*)g_wa[3])[i];
        s0 += xv.x * v0.x + xv.y * v0.y + xv.z * v0.z + xv.w * v0.w;
        s1 += xv.x * v1.x + xv.y * v1.y + xv.z * v1.z + xv.w * v1.w;
        s2 += xv.x * v2.x + xv.y * v2.y + xv.z * v2.z + xv.w * v2.w;
        s3 += xv.x * v3.x + xv.y * v3.y + xv.z * v3.z + xv.w * v3.w;
    }
#pragma unroll
    for (int o = 16; o > 0; o >>= 1) {
        s0 += __shfl_xor_sync(0xffffffffu, s0, o);
        s1 += __shfl_xor_sync(0xffffffffu, s1, o);
        s2 += __shfl_xor_sync(0xffffffffu, s2, o);
        s3 += __shfl_xor_sync(0xffffffffu, s3, o);
    }
    if (lane == 0) {
        g_as1[n] = s0; g_ad1[n] = s1;
        g_as2[n] = s2; g_ad2[n] = s3;
    }
}

// ---------------- bf16 split helpers + mma -------------------------------------
__device__ __forceinline__ void pack2(float e0, float e1, unsigned& h, unsigned& l) {
    __nv_bfloat16 h0 = __float2bfloat16(e0);
    __nv_bfloat16 h1 = __float2bfloat16(e1);
    float r0 = e0 - __bfloat162float(h0);
    float r1 = e1 - __bfloat162float(h1);
    __nv_bfloat16 l0 = __float2bfloat16(r0);
    __nv_bfloat16 l1 = __float2bfloat16(r1);
    __nv_bfloat162 hh; hh.x = h0; hh.y = h1;   // .x = low 16 bits = lower-k element
    __nv_bfloat162 ll; ll.x = l0; ll.y = l1;
    h = *reinterpret_cast<unsigned*>(&hh);
    l = *reinterpret_cast<unsigned*>(&ll);
}

#define MMA16(C, A0, A1, A2, A3, B0, B1)                                        \
    asm volatile("mma.sync.aligned.m16n8k16.row.col.f32.bf16.bf16.f32 "         \
                 "{%0,%1,%2,%3}, {%4,%5,%6,%7}, {%8,%9}, {%0,%1,%2,%3};"        \
                 : "+f"((C)[0]), "+f"((C)[1]), "+f"((C)[2]), "+f"((C)[3])       \
                 : "r"(A0), "r"(A1), "r"(A2), "r"(A3), "r"(B0), "r"(B1))

// smem tile geometry: BM=128, BN=128, BK=32 fp32 (=16 bf16x2 pairs along K)
#define ASTR 20     // uint32 stride per A row (16 pairs + pad; 20 mod 32/4 -> conflict-free)
#define BSTR 132    // uint32 stride per B k2-row (128 + pad)

// ---------------- dual GEMM: H1 = x@W1, H2 = x@W2 (grid.x 0..7 -> W1, 8..15 -> W2)
__global__ __launch_bounds__(256)
void gemm_dual(const float* __restrict__ A, const float* __restrict__ W1,
               const float* __restrict__ W2) {
    __shared__ unsigned AsH[128 * ASTR], AsL[128 * ASTR];
    __shared__ unsigned BsH[16 * BSTR],  BsL[16 * BSTR];

    int tid = threadIdx.x;
    int lane = tid & 31, warp = tid >> 5;
    int wm = warp & 3, wn = warp >> 2;
    int which = blockIdx.x >> 3;
    int bnl = (blockIdx.x & 7) * 128;
    int bm = blockIdx.y * 128;
    const float* B = which ? W2 : W1;

    float acc[2][8][4];
#pragma unroll
    for (int a = 0; a < 2; a++)
#pragma unroll
        for (int b = 0; b < 8; b++)
#pragma unroll
            for (int c = 0; c < 4; c++) acc[a][b][c] = 0.f;

    for (int kt = 0; kt < INC; kt += 32) {
        // load A tile 128x32
#pragma unroll
        for (int i = 0; i < 4; i++) {
            int q = tid + 256 * i;
            int row = q >> 3, f4 = q & 7;
            int grow = bm + row;
            float4 v = make_float4(0.f, 0.f, 0.f, 0.f);
            if (grow < NN) v = *(const float4*)(A + (size_t)grow * INC + kt + f4 * 4);
            unsigned h0, h1, l0, l1;
            pack2(v.x, v.y, h0, l0);
            pack2(v.z, v.w, h1, l1);
            int o = row * ASTR + f4 * 2;
            AsH[o] = h0; AsH[o + 1] = h1;
            AsL[o] = l0; AsL[o + 1] = l1;
        }
        // load B tile 32x128 -> pairs [k2][n]
#pragma unroll
        for (int i = 0; i < 2; i++) {
            int q = tid + 256 * i;
            int k2 = q >> 5;
            int n4 = (q & 31) * 4;
            const float* b0p = B + (size_t)(kt + 2 * k2) * OUTC + bnl + n4;
            float4 r0 = *(const float4*)b0p;
            float4 r1 = *(const float4*)(b0p + OUTC);
            unsigned h[4], l[4];
            pack2(r0.x, r1.x, h[0], l[0]);
            pack2(r0.y, r1.y, h[1], l[1]);
            pack2(r0.z, r1.z, h[2], l[2]);
            pack2(r0.w, r1.w, h[3], l[3]);
            int o = k2 * BSTR + n4;
            *(uint4*)&BsH[o] = make_uint4(h[0], h[1], h[2], h[3]);
            *(uint4*)&BsL[o] = make_uint4(l[0], l[1], l[2], l[3]);
        }
        __syncthreads();
#pragma unroll
        for (int ks = 0; ks < 2; ks++) {
            int kb = ks * 8 + (lane & 3);
            unsigned bh[8][2], bl[8][2];
#pragma unroll
            for (int nf = 0; nf < 8; nf++) {
                int n = wn * 64 + nf * 8 + (lane >> 2);
                bh[nf][0] = BsH[kb * BSTR + n];
                bh[nf][1] = BsH[(kb + 4) * BSTR + n];
                bl[nf][0] = BsL[kb * BSTR + n];
                bl[nf][1] = BsL[(kb + 4) * BSTR + n];
            }
#pragma unroll
            for (int mf = 0; mf < 2; mf++) {
                int r0 = wm * 32 + mf * 16 + (lane >> 2);
                unsigned ah0 = AsH[r0 * ASTR + kb];
                unsigned ah1 = AsH[(r0 + 8) * ASTR + kb];
                unsigned ah2 = AsH[r0 * ASTR + kb + 4];
                unsigned ah3 = AsH[(r0 + 8) * ASTR + kb + 4];
                unsigned al0 = AsL[r0 * ASTR + kb];
                unsigned al1 = AsL[(r0 + 8) * ASTR + kb];
                unsigned al2 = AsL[r0 * ASTR + kb + 4];
                unsigned al3 = AsL[(r0 + 8) * ASTR + kb + 4];
#pragma unroll
                for (int nf = 0; nf < 8; nf++) {
                    MMA16(acc[mf][nf], ah0, ah1, ah2, ah3, bh[nf][0], bh[nf][1]);
                    MMA16(acc[mf][nf], ah0, ah1, ah2, ah3, bl[nf][0], bl[nf][1]);
                    MMA16(acc[mf][nf], al0, al1, al2, al3, bh[nf][0], bh[nf][1]);
                }
            }
        }
        __syncthreads();
    }

    float* H = which ? g_H2 : g_H1;
#pragma unroll
    for (int mf = 0; mf < 2; mf++) {
        int row = bm + wm * 32 + mf * 16 + (lane >> 2);
#pragma unroll
        for (int nf = 0; nf < 8; nf++) {
            int col = bnl + wn * 64 + nf * 8 + (lane & 3) * 2;
            if (row < NN)
                *(float2*)&H[(size_t)row * OUTC + col] = make_float2(acc[mf][nf][0], acc[mf][nf][1]);
            if (row + 8 < NN)
                *(float2*)&H[(size_t)(row + 8) * OUTC + col] = make_float2(acc[mf][nf][2], acc[mf][nf][3]);
        }
    }
}

// ---------------- colsum GEMM: csum += colsum(tanh((h1p+h2p)@Wp1 + bp1)) --------
__global__ __launch_bounds__(256)
void gemm_colsum(const float* __restrict__ Wp1, const float* __restrict__ bp1) {
    __shared__ unsigned AsH[128 * ASTR], AsL[128 * ASTR];
    __shared__ unsigned BsH[16 * BSTR],  BsL[16 * BSTR];
    __shared__ float scl[4][128];

    int tid = threadIdx.x;
    int lane = tid & 31, warp = tid >> 5;
    int wm = warp & 3, wn = warp >> 2;
    int bn = blockIdx.x * 128;
    int bm = blockIdx.y * 128;

    float acc[2][8][4];
#pragma unroll
    for (int a = 0; a < 2; a++)
#pragma unroll
        for (int b = 0; b < 8; b++)
#pragma unroll
            for (int c = 0; c < 4; c++) acc[a][b][c] = 0.f;

    for (int kt = 0; kt < OUTC; kt += 32) {
#pragma unroll
        for (int i = 0; i < 4; i++) {
            int q = tid + 256 * i;
            int row = q >> 3, f4 = q & 7;
            int grow = bm + row;
            float4 v = make_float4(0.f, 0.f, 0.f, 0.f);
            if (grow < NN) {
                size_t off = (size_t)grow * OUTC + kt + f4 * 4;
                float4 v1 = *(const float4*)(g_h1p + off);
                float4 v2 = *(const float4*)(g_h2p + off);
                v.x = v1.x + v2.x; v.y = v1.y + v2.y;
                v.z = v1.z + v2.z; v.w = v1.w + v2.w;
            }
            unsigned h0, h1, l0, l1;
            pack2(v.x, v.y, h0, l0);
            pack2(v.z, v.w, h1, l1);
            int o = row * ASTR + f4 * 2;
            AsH[o] = h0; AsH[o + 1] = h1;
            AsL[o] = l0; AsL[o + 1] = l1;
        }
#pragma unroll
        for (int i = 0; i < 2; i++) {
            int q = tid + 256 * i;
            int k2 = q >> 5;
            int n4 = (q & 31) * 4;
            const float* b0p = Wp1 + (size_t)(kt + 2 * k2) * OUTC + bn + n4;
            float4 r0 = *(const float4*)b0p;
            float4 r1 = *(const float4*)(b0p + OUTC);
            unsigned h[4], l[4];
            pack2(r0.x, r1.x, h[0], l[0]);
            pack2(r0.y, r1.y, h[1], l[1]);
            pack2(r0.z, r1.z, h[2], l[2]);
            pack2(r0.w, r1.w, h[3], l[3]);
            int o = k2 * BSTR + n4;
            *(uint4*)&BsH[o] = make_uint4(h[0], h[1], h[2], h[3]);
            *(uint4*)&BsL[o] = make_uint4(l[0], l[1], l[2], l[3]);
        }
        __syncthreads();
#pragma unroll
        for (int ks = 0; ks < 2; ks++) {
            int kb = ks * 8 + (lane & 3);
            unsigned bh[8][2], bl[8][2];
#pragma unroll
            for (int nf = 0; nf < 8; nf++) {
                int n = wn * 64 + nf * 8 + (lane >> 2);
                bh[nf][0] = BsH[kb * BSTR + n];
                bh[nf][1] = BsH[(kb + 4) * BSTR + n];
                bl[nf][0] = BsL[kb * BSTR + n];
                bl[nf][1] = BsL[(kb + 4) * BSTR + n];
            }
#pragma unroll
            for (int mf = 0; mf < 2; mf++) {
                int r0 = wm * 32 + mf * 16 + (lane >> 2);
                unsigned ah0 = AsH[r0 * ASTR + kb];
                unsigned ah1 = AsH[(r0 + 8) * ASTR + kb];
                unsigned ah2 = AsH[r0 * ASTR + kb + 4];
                unsigned ah3 = AsH[(r0 + 8) * ASTR + kb + 4];
                unsigned al0 = AsL[r0 * ASTR + kb];
                unsigned al1 = AsL[(r0 + 8) * ASTR + kb];
                unsigned al2 = AsL[r0 * ASTR + kb + 4];
                unsigned al3 = AsL[(r0 + 8) * ASTR + kb + 4];
#pragma unroll
                for (int nf = 0; nf < 8; nf++) {
                    MMA16(acc[mf][nf], ah0, ah1, ah2, ah3, bh[nf][0], bh[nf][1]);
                    MMA16(acc[mf][nf], ah0, ah1, ah2, ah3, bl[nf][0], bl[nf][1]);
                    MMA16(acc[mf][nf], al0, al1, al2, al3, bh[nf][0], bh[nf][1]);
                }
            }
        }
        __syncthreads();
    }

    // epilogue: tanh + bias, column-sum over valid rows
    int rbase = bm + wm * 32 + (lane >> 2);
    bool v00 = (rbase) < NN;
    bool v01 = (rbase + 8) < NN;
    bool v10 = (rbase + 16) < NN;
    bool v11 = (rbase + 24) < NN;
#pragma unroll
    for (int nf = 0; nf < 8; nf++) {
#pragma unroll
        for (int cc = 0; cc < 2; cc++) {
            int col = bn + wn * 64 + nf * 8 + (lane & 3) * 2 + cc;
            float b = bp1[col];
            float s = 0.f;
            if (v00) s += tanhf(acc[0][nf][cc] + b);
            if (v01) s += tanhf(acc[0][nf][cc + 2] + b);
            if (v10) s += tanhf(acc[1][nf][cc] + b);
            if (v11) s += tanhf(acc[1][nf][cc + 2] + b);
            s += __shfl_xor_sync(0xffffffffu, s, 4);
            s += __shfl_xor_sync(0xffffffffu, s, 8);
            s += __shfl_xor_sync(0xffffffffu, s, 16);
            if (lane < 4) scl[wm][wn * 64 + nf * 8 + lane * 2 + cc] = s;
        }
    }
    __syncthreads();
    if (tid < 128) {
        float s = scl[0][tid] + scl[1][tid] + scl[2][tid] + scl[3][tid];
        atomicAdd(&g_csum[bn + tid], s);
    }
}

// ---------------- per-dst-node segment softmax + weighted aggregation ----------
__global__ __launch_bounds__(256)
void k_agg(const float* __restrict__ b1, const float* __restrict__ b2,
           const float* __restrict__ prelu_a) {
    int d = blockIdx.x;
    int tid = threadIdx.x;
    int beg = g_rowptr[d];
    int deg = g_rowptr[d + 1] - beg;
    float ad1 = g_ad1[d];
    float ad2 = g_ad2[d];

    __shared__ float r1[256];
    __shared__ float r2[256];

    float m1 = -1e30f, m2 = -1e30f;
    for (int i = tid; i < deg; i += 256) {
        int s = g_csrc[beg + i];
        float e1 = g_as1[s] + ad1; e1 = (e1 >= 0.f) ? e1 : 0.2f * e1;
        float e2 = g_as2[s] + ad2; e2 = (e2 >= 0.f) ? e2 : 0.2f * e2;
        m1 = fmaxf(m1, e1);
        m2 = fmaxf(m2, e2);
    }
    r1[tid] = m1; r2[tid] = m2;
    __syncthreads();
    for (int o = 128; o > 0; o >>= 1) {
        if (tid < o) {
            r1[tid] = fmaxf(r1[tid], r1[tid + o]);
            r2[tid] = fmaxf(r2[tid], r2[tid + o]);
        }
        __syncthreads();
    }
    float M1 = r1[0], M2 = r2[0];
    __syncthreads();

    float s1 = 0.f, s2 = 0.f;
    for (int i = tid; i < deg; i += 256) {
        int s = g_csrc[beg + i];
        float e1 = g_as1[s] + ad1; e1 = (e1 >= 0.f) ? e1 : 0.2f * e1;
        float e2 = g_as2[s] + ad2; e2 = (e2 >= 0.f) ? e2 : 0.2f * e2;
        s1 += expf(e1 - M1);
        s2 += expf(e2 - M2);
    }
    r1[tid] = s1; r2[tid] = s2;
    __syncthreads();
    for (int o = 128; o > 0; o >>= 1) {
        if (tid < o) {
            r1[tid] += r1[tid + o];
            r2[tid] += r2[tid + o];
        }
        __syncthreads();
    }
    float inv1 = 1.f / r1[0];
    float inv2 = 1.f / r2[0];
    __syncthreads();

    __shared__ int   sS[128];
    __shared__ float sA1[128];
    __shared__ float sA2[128];

    int c = tid * 4;
    float4 acc1 = make_float4(0.f, 0.f, 0.f, 0.f);
    float4 acc2 = make_float4(0.f, 0.f, 0.f, 0.f);

    for (int base = 0; base < deg; base += 128) {
        int cn = min(128, deg - base);
        if (tid < cn) {
            int s = g_csrc[beg + base + tid];
            float e1 = g_as1[s] + ad1; e1 = (e1 >= 0.f) ? e1 : 0.2f * e1;
            float e2 = g_as2[s] + ad2; e2 = (e2 >= 0.f) ? e2 : 0.2f * e2;
            sS[tid]  = s;
            sA1[tid] = expf(e1 - M1) * inv1;
            sA2[tid] = expf(e2 - M2) * inv2;
        }
        __syncthreads();
        for (int i = 0; i < cn; i++) {
            int s = sS[i];
            float a1 = sA1[i], a2 = sA2[i];
            float4 v1 = *(const float4*)(g_H1 + (size_t)s * OUTC + c);
            float4 v2 = *(const float4*)(g_H2 + (size_t)s * OUTC + c);
            acc1.x += a1 * v1.x; acc1.y += a1 * v1.y; acc1.z += a1 * v1.z; acc1.w += a1 * v1.w;
            acc2.x += a2 * v2.x; acc2.y += a2 * v2.y; acc2.z += a2 * v2.z; acc2.w += a2 * v2.w;
        }
        __syncthreads();
    }

    float pa = *prelu_a;
    float4 bb1 = *(const float4*)(b1 + c);
    float4 bb2 = *(const float4*)(b2 + c);
    float4 h1, h2;
    h1.x = acc1.x + bb1.x; h1.y = acc1.y + bb1.y; h1.z = acc1.z + bb1.z; h1.w = acc1.w + bb1.w;
    h2.x = acc2.x + bb2.x; h2.y = acc2.y + bb2.y; h2.z = acc2.z + bb2.z; h2.w = acc2.w + bb2.w;
    h1.x = (h1.x >= 0.f) ? h1.x : pa * h1.x;
    h1.y = (h1.y >= 0.f) ? h1.y : pa * h1.y;
    h1.z = (h1.z >= 0.f) ? h1.z : pa * h1.z;
    h1.w = (h1.w >= 0.f) ? h1.w : pa * h1.w;
    h2.x = (h2.x >= 0.f) ? h2.x : pa * h2.x;
    h2.y = (h2.y >= 0.f) ? h2.y : pa * h2.y;
    h2.z = (h2.z >= 0.f) ? h2.z : pa * h2.z;
    h2.w = (h2.w >= 0.f) ? h2.w : pa * h2.w;

    size_t off = (size_t)d * OUTC + c;
    *(float4*)(g_h1p + off) = h1;
    *(float4*)(g_h2p + off) = h2;
}

// ---------------- semantic attention: w = (csum/N) @ Wp2, softmax ----------------
__global__ __launch_bounds__(256)
void k_att(const float* __restrict__ Wp2) {
    __shared__ float tb[OUTC];
    int tid = threadIdx.x;
    for (int i = tid; i < OUTC; i += 256) tb[i] = g_csum[i] * (1.0f / (float)NN);
    __syncthreads();
    int j0 = tid * 4;
    float4 w = make_float4(0.f, 0.f, 0.f, 0.f);
    for (int i = 0; i < OUTC; i++) {
        float t = tb[i];
        float4 v = *(const float4*)(Wp2 + (size_t)i * OUTC + j0);
        w.x += t * v.x; w.y += t * v.y; w.z += t * v.z; w.w += t * v.w;
    }
    __shared__ float rr[256];
    float lm = fmaxf(fmaxf(w.x, w.y), fmaxf(w.z, w.w));
    rr[tid] = lm;
    __syncthreads();
    for (int o = 128; o > 0; o >>= 1) {
        if (tid < o) rr[tid] = fmaxf(rr[tid], rr[tid + o]);
        __syncthreads();
    }
    float M = rr[0];
    __syncthreads();
    float ex = expf(w.x - M), ey = expf(w.y - M), ez = expf(w.z - M), ew = expf(w.w - M);
    rr[tid] = ex + ey + ez + ew;
    __syncthreads();
    for (int o = 128; o > 0; o >>= 1) {
        if (tid < o) rr[tid] += rr[tid + o];
        __syncthreads();
    }
    float inv = 1.f / rr[0];
    *(float4*)(g_att + j0) = make_float4(ex * inv, ey * inv, ez * inv, ew * inv);
}

// ---------------- final blend ----------------
__global__ void k_final(float* __restrict__ out) {
    int i = blockIdx.x * blockDim.x + threadIdx.x;
    if (i >= NN * OUTC / 4) return;
    int cg = i & (OUTC / 4 - 1);
    float4 a  = *(const float4*)(g_att + cg * 4);
    float4 h1 = ((const float4*)g_h1p)[i];
    float4 h2 = ((const float4*)g_h2p)[i];
    float4 o;
    o.x = a.x * h1.x + (1.f - a.x) * h2.x;
    o.y = a.y * h1.y + (1.f - a.y) * h2.y;
    o.z = a.z * h1.z + (1.f - a.z) * h2.z;
    o.w = a.w * h1.w + (1.f - a.w) * h2.w;
    ((float4*)out)[i] = o;
}

// ---------------- launch ----------------
extern "C" void kernel_launch(void* const* d_in, const int* in_sizes, int n_in,
                              void* d_out, int out_size) {
    const float* x      = (const float*)d_in[0];
    const int*   ei     = (const int*)d_in[1];
    const float* W1     = (const float*)d_in[2];
    const float* a_src1 = (const float*)d_in[3];
    const float* a_dst1 = (const float*)d_in[4];
    const float* b1     = (const float*)d_in[5];
    const float* W2     = (const float*)d_in[6];
    const float* a_src2 = (const float*)d_in[7];
    const float* a_dst2 = (const float*)d_in[8];
    const float* b2     = (const float*)d_in[9];
    const float* prelua = (const float*)d_in[10];
    const float* Wp1    = (const float*)d_in[11];
    const float* bp1    = (const float*)d_in[12];
    const float* Wp2    = (const float*)d_in[13];
    float* out = (float*)d_out;

    k_init<<<(NN + 255) / 256, 256>>>();
    k_wa<<<16, 256>>>(W1, a_src1, a_dst1, W2, a_src2, a_dst2);
    k_xdots<<<NN / 8, 256>>>(x);
    k_count<<<(ET + 255) / 256, 256>>>(ei);
    k_scan<<<1, 1024>>>();
    k_scatter<<<(ET + 255) / 256, 256>>>(ei);
    gemm_dual<<<dim3(16, (NN + 127) / 128), 256>>>(x, W1, W2);
    k_agg<<<NN, 256>>>(b1, b2, prelua);
    gemm_colsum<<<dim3(8, (NN + 127) / 128), 256>>>(Wp1, bp1);
    k_att<<<1, 256>>>(Wp2);
    k_final<<<(NN * OUTC / 4 + 255) / 256, 256>>>(out);
}